// round 9
// baseline (speedup 1.0000x reference)
#include <cuda_runtime.h>

// NeighborhoodAggregation via counting-sort (rank-precomputed, atomic-free scatter)
// + warp-per-node register reduction.
// out = (Z[node] + sum_{e: dst=node} Z[src_e]) / (deg(node)+1)
// Inputs: Z_real (100000*64 f32), Z_imag (100000*64 f32), edge_index (2*1600000 int32)
// Output: float32 [A_real ; A_imag]

#define MAX_NODES 100352
#define MAX_EDGES 1600000
#define SCAN_BLOCK 256
#define SCAN_PER_THREAD 4
#define SCAN_TILE (SCAN_BLOCK * SCAN_PER_THREAD)   // 1024 elements per block
#define MAX_SCAN_BLOCKS 128                        // ceil(100352/1024) = 98

__device__ int g_counts[MAX_NODES];       // in-degree (edges only)
__device__ int g_offsets[MAX_NODES];      // exclusive prefix of counts
__device__ int g_rank[MAX_EDGES];         // rank of edge within its dst bucket
__device__ int g_sorted[MAX_EDGES];       // src indices grouped by dst
__device__ int g_blocksum[MAX_SCAN_BLOCKS];

// ---- Pass 0: zero counts ----
__global__ void zero_kernel(int n_nodes)
{
    int i = blockIdx.x * blockDim.x + threadIdx.x;
    if (i < n_nodes) g_counts[i] = 0;
}

// ---- Pass 1: histogram of dst, capturing per-edge rank ----
__global__ void rank_kernel(const int* __restrict__ dst, int n_edges)
{
    int base = (blockIdx.x * blockDim.x + threadIdx.x) * 4;
#pragma unroll
    for (int q = 0; q < 4; q++) {
        int i = base + q;
        if (i < n_edges) {
            g_rank[i] = atomicAdd(&g_counts[dst[i]], 1);
        }
    }
}

// ---- Pass 2a: per-block sums of counts ----
__global__ void scan_blocksum_kernel(int n_nodes)
{
    __shared__ int sdata[SCAN_BLOCK];
    int t = threadIdx.x;
    int base = blockIdx.x * SCAN_TILE + t * SCAN_PER_THREAD;
    int s = 0;
#pragma unroll
    for (int q = 0; q < SCAN_PER_THREAD; q++) {
        int i = base + q;
        if (i < n_nodes) s += g_counts[i];
    }
    sdata[t] = s;
    __syncthreads();
    for (int off = SCAN_BLOCK / 2; off > 0; off >>= 1) {
        if (t < off) sdata[t] += sdata[t + off];
        __syncthreads();
    }
    if (t == 0) g_blocksum[blockIdx.x] = sdata[0];
}

// ---- Pass 2b: single small block scans the block sums (exclusive) ----
__global__ void scan_top_kernel(int n_blocks)
{
    __shared__ int sdata[MAX_SCAN_BLOCKS];
    int t = threadIdx.x;
    sdata[t] = (t < n_blocks) ? g_blocksum[t] : 0;
    __syncthreads();
    for (int off = 1; off < MAX_SCAN_BLOCKS; off <<= 1) {
        int v = (t >= off) ? sdata[t - off] : 0;
        __syncthreads();
        sdata[t] += v;
        __syncthreads();
    }
    if (t < n_blocks) g_blocksum[t] = (t > 0) ? sdata[t - 1] : 0;  // exclusive
}

// ---- Pass 2c: per-block rescan, write offsets ----
__global__ void scan_write_kernel(int n_nodes)
{
    __shared__ int sdata[SCAN_BLOCK];
    int t = threadIdx.x;
    int base = blockIdx.x * SCAN_TILE + t * SCAN_PER_THREAD;

    int c[SCAN_PER_THREAD];
    int s = 0;
#pragma unroll
    for (int q = 0; q < SCAN_PER_THREAD; q++) {
        int i = base + q;
        c[q] = (i < n_nodes) ? g_counts[i] : 0;
        s += c[q];
    }
    sdata[t] = s;
    __syncthreads();
    for (int off = 1; off < SCAN_BLOCK; off <<= 1) {
        int v = (t >= off) ? sdata[t - off] : 0;
        __syncthreads();
        sdata[t] += v;
        __syncthreads();
    }
    int run = g_blocksum[blockIdx.x] + ((t > 0) ? sdata[t - 1] : 0);
#pragma unroll
    for (int q = 0; q < SCAN_PER_THREAD; q++) {
        int i = base + q;
        if (i < n_nodes) {
            g_offsets[i] = run;
            run += c[q];
        }
    }
}

// ---- Pass 3: atomic-free scatter: pos = offsets[dst] + rank ----
__global__ void scatter_kernel(const int* __restrict__ src,
                               const int* __restrict__ dst,
                               int n_edges)
{
    int base = (blockIdx.x * blockDim.x + threadIdx.x) * 4;
    if (base + 4 <= n_edges) {
        int d0 = dst[base + 0], d1 = dst[base + 1], d2 = dst[base + 2], d3 = dst[base + 3];
        int r0 = g_rank[base + 0], r1 = g_rank[base + 1], r2 = g_rank[base + 2], r3 = g_rank[base + 3];
        int s0 = src[base + 0], s1 = src[base + 1], s2 = src[base + 2], s3 = src[base + 3];
        int p0 = g_offsets[d0] + r0;
        int p1 = g_offsets[d1] + r1;
        int p2 = g_offsets[d2] + r2;
        int p3 = g_offsets[d3] + r3;
        g_sorted[p0] = s0;
        g_sorted[p1] = s1;
        g_sorted[p2] = s2;
        g_sorted[p3] = s3;
    } else {
        for (int i = base; i < n_edges; i++) {
            g_sorted[g_offsets[dst[i]] + g_rank[i]] = src[i];
        }
    }
}

// ---- Pass 4: warp-per-node register reduction ----
// Lane l: l<16 -> real chunk l, l>=16 -> imag chunk l-16.
// Per edge, the full warp reads one 1KB row (512B real + 512B imag), coalesced.
__global__ void agg_kernel(const float4* __restrict__ zr,
                           const float4* __restrict__ zi,
                           float4* __restrict__ outr,
                           float4* __restrict__ outi,
                           int n_nodes)
{
    int warp_in_block = threadIdx.x >> 5;
    int node = blockIdx.x * (blockDim.x >> 5) + warp_in_block;
    if (node >= n_nodes) return;
    int lane = threadIdx.x & 31;

    const float4* __restrict__ zbase = (lane < 16) ? zr : zi;
    int chunk = lane & 15;

    // self-loop contribution
    float4 acc = zbase[(size_t)node * 16 + chunk];

    int base = g_offsets[node];
    int cnt = g_counts[node];
    const int* __restrict__ idx = g_sorted + base;

    int k = 0;
    for (; k + 8 <= cnt; k += 8) {
        int s0 = idx[k + 0];
        int s1 = idx[k + 1];
        int s2 = idx[k + 2];
        int s3 = idx[k + 3];
        int s4 = idx[k + 4];
        int s5 = idx[k + 5];
        int s6 = idx[k + 6];
        int s7 = idx[k + 7];
        float4 v0 = zbase[(size_t)s0 * 16 + chunk];
        float4 v1 = zbase[(size_t)s1 * 16 + chunk];
        float4 v2 = zbase[(size_t)s2 * 16 + chunk];
        float4 v3 = zbase[(size_t)s3 * 16 + chunk];
        float4 v4 = zbase[(size_t)s4 * 16 + chunk];
        float4 v5 = zbase[(size_t)s5 * 16 + chunk];
        float4 v6 = zbase[(size_t)s6 * 16 + chunk];
        float4 v7 = zbase[(size_t)s7 * 16 + chunk];
        acc.x += ((v0.x + v1.x) + (v2.x + v3.x)) + ((v4.x + v5.x) + (v6.x + v7.x));
        acc.y += ((v0.y + v1.y) + (v2.y + v3.y)) + ((v4.y + v5.y) + (v6.y + v7.y));
        acc.z += ((v0.z + v1.z) + (v2.z + v3.z)) + ((v4.z + v5.z) + (v6.z + v7.z));
        acc.w += ((v0.w + v1.w) + (v2.w + v3.w)) + ((v4.w + v5.w) + (v6.w + v7.w));
    }
    for (; k + 2 <= cnt; k += 2) {
        int s0 = idx[k + 0];
        int s1 = idx[k + 1];
        float4 v0 = zbase[(size_t)s0 * 16 + chunk];
        float4 v1 = zbase[(size_t)s1 * 16 + chunk];
        acc.x += v0.x + v1.x;
        acc.y += v0.y + v1.y;
        acc.z += v0.z + v1.z;
        acc.w += v0.w + v1.w;
    }
    if (k < cnt) {
        int s0 = idx[k];
        float4 v0 = zbase[(size_t)s0 * 16 + chunk];
        acc.x += v0.x; acc.y += v0.y; acc.z += v0.z; acc.w += v0.w;
    }

    float inv = 1.0f / (float)(cnt + 1);
    acc.x *= inv; acc.y *= inv; acc.z *= inv; acc.w *= inv;

    float4* __restrict__ obase = (lane < 16) ? outr : outi;
    obase[(size_t)node * 16 + chunk] = acc;
}

extern "C" void kernel_launch(void* const* d_in, const int* in_sizes, int n_in,
                              void* d_out, int out_size)
{
    const float* Z_real = (const float*)d_in[0];
    const float* Z_imag = (const float*)d_in[1];
    const int* edge_index = (const int*)d_in[2];

    int n_nodes = in_sizes[0] / 64;
    int n_edges = in_sizes[2] / 2;

    const int* src = edge_index;
    const int* dst = edge_index + n_edges;

    float* out_real = (float*)d_out;
    float* out_imag = (float*)d_out + (size_t)n_nodes * 64;

    int threads = 256;
    int n_scan_blocks = (n_nodes + SCAN_TILE - 1) / SCAN_TILE;
    int edge4_blocks = ((n_edges + 3) / 4 + threads - 1) / threads;

    zero_kernel<<<(n_nodes + threads - 1) / threads, threads>>>(n_nodes);
    rank_kernel<<<edge4_blocks, threads>>>(dst, n_edges);
    scan_blocksum_kernel<<<n_scan_blocks, SCAN_BLOCK>>>(n_nodes);
    scan_top_kernel<<<1, MAX_SCAN_BLOCKS>>>(n_scan_blocks);
    scan_write_kernel<<<n_scan_blocks, SCAN_BLOCK>>>(n_nodes);
    scatter_kernel<<<edge4_blocks, threads>>>(src, dst, n_edges);

    {
        int warps_per_block = threads / 32;  // 8 nodes per block
        int blocks = (n_nodes + warps_per_block - 1) / warps_per_block;
        agg_kernel<<<blocks, threads>>>((const float4*)Z_real, (const float4*)Z_imag,
                                        (float4*)out_real, (float4*)out_imag, n_nodes);
    }
}